// round 7
// baseline (speedup 1.0000x reference)
#include <cuda_runtime.h>
#include <math.h>
#include <stdint.h>

// Problem constants
#define BB     32
#define LL     4096
#define DIN    150
#define DST    75
#define HID    75
#define HIDP   80        // padded hidden (W1 pad = 0)
#define K2N    75        // DIN/2 k-pairs
#define TILE_L 128
#define NCHUNK (LL / TILE_L)   // 32
#define XT_STR 130       // xs_t row stride in float2 units (EVEN -> 16B-aligned rows)
#define NTH    512       // kernel2 threads (16 tx x 32 ty)

typedef unsigned long long ull;

// scratch: state projection + b0, padded to HIDP
__device__ float g_spb[BB * HIDP];
// partial weighted sums and exp-sums (deterministic two-stage reduction)
__device__ float g_part[BB][NCHUNK][160];
__device__ float g_psum[BB][NCHUNK];

// ---------------------------------------------------------------------------
// Kernel 1: spb[b][j] = b0[j] + state[b] . W0[0:75, j]
// 4-way k-split to shorten the dependent LDG chain.
// ---------------------------------------------------------------------------
__global__ __launch_bounds__(320)
void k_stateproj(const float* __restrict__ state,
                 const float* __restrict__ W0,
                 const float* __restrict__ b0) {
    __shared__ float red[4][HIDP];
    const int b     = blockIdx.x;
    const int j     = threadIdx.x % HIDP;     // 0..79
    const int slice = threadIdx.x / HIDP;     // 0..3
    float acc = 0.0f;
    if (j < HID) {
        const float* st = state + b * DST;
        const int k0 = slice * 19;
        const int k1 = min(k0 + 19, DST);
#pragma unroll 19
        for (int k = k0; k < k1; ++k)
            acc = fmaf(st[k], W0[k * HID + j], acc);
    }
    red[slice][j] = acc;
    __syncthreads();
    if (slice == 0) {
        float v = (j < HID)
            ? (red[0][j] + red[1][j]) + (red[2][j] + red[3][j]) + b0[j]
            : 0.0f;
        g_spb[b * HIDP + j] = v;
    }
}

// packed fp32x2 FMA (Blackwell FFMA2 — PTX-only path)
__device__ __forceinline__ void ffma2(ull& d, ull a, ull b) {
    asm("fma.rn.f32x2 %0, %1, %2, %0;" : "+l"(d) : "l"(a), "l"(b));
}

// ---------------------------------------------------------------------------
// Kernel 2: fused scores + softmax-numerator partials.
// 512 threads, thread tile 4 rows x 5 cols. x tile TRANSPOSED as
// xs_t[k2][row] (float2 = k-pair): xv = 2 x LDS.128 broadcast; wv = 5 x
// LDS.64 conflict-free (banks tx*10 mod 32 distinct).
// ---------------------------------------------------------------------------
__global__ __launch_bounds__(NTH, 1)
void k_scores(const float* __restrict__ inputs,
              const float* __restrict__ W0,
              const float* __restrict__ W1,
              const float* __restrict__ b1,
              const int* __restrict__ cmask,
              float* __restrict__ s1_out) {
    extern __shared__ float sm[];
    float* xs_t = sm;                                      // [K2N][XT_STR] float2
    float2* ws2 = (float2*)(sm + K2N * XT_STR * 2);        // [K2N][HIDP] k-pairs
    float* spb_s = (float*)(ws2 + K2N * HIDP);             // [HIDP]
    float* w1s   = spb_s + HIDP;                           // [HIDP]
    float* es    = w1s + HIDP;                             // [TILE_L]
    float* psred = es + TILE_L;                            // [4]

    const int b     = blockIdx.y;
    const int chunk = blockIdx.x;
    const int l0    = chunk * TILE_L;
    const int tid   = threadIdx.x;

    // --- stage input tile transposed: xs_t[k2][r] = (x[r][2k2], x[r][2k2+1])
    {
        const float2* gin = (const float2*)(inputs + ((size_t)b * LL + l0) * DIN);
        float2* xt2 = (float2*)xs_t;
        for (int idx = tid; idx < K2N * TILE_L; idx += NTH) {
            int r  = idx & (TILE_L - 1);
            int k2 = idx >> 7;
            xt2[k2 * XT_STR + r] = gin[(size_t)r * K2N + k2];
        }
    }
    // --- stage W0 input-part, repacked as k-pairs ---
    for (int idx = tid; idx < K2N * HIDP; idx += NTH) {
        int k2 = idx / HIDP;
        int j  = idx - k2 * HIDP;
        float2 w;
        if (j < HID) {
            w.x = W0[(DST + 2 * k2)     * HID + j];
            w.y = W0[(DST + 2 * k2 + 1) * HID + j];
        } else { w.x = 0.0f; w.y = 0.0f; }
        ws2[idx] = w;
    }
    if (tid < HIDP) {
        spb_s[tid] = g_spb[b * HIDP + tid];
        w1s[tid]   = (tid < HID) ? W1[tid] : 0.0f;
    }
    __syncthreads();

    const int tx = tid & 15;          // col group: cols tx*5 .. tx*5+4
    const int ty = tid >> 4;          // row group: rows ty*4 .. ty*4+3
    const int r0 = ty * 4;

    ull acc[4][5];
#pragma unroll
    for (int i = 0; i < 4; ++i)
#pragma unroll
        for (int c = 0; c < 5; ++c) acc[i][c] = 0ULL;

    const ull* xbase = (const ull*)xs_t + r0;        // + k2*XT_STR (even)
    const ull* wbase = (const ull*)ws2 + tx * 5;     // + k2*HIDP

#pragma unroll 5
    for (int k2 = 0; k2 < K2N; ++k2) {
        // 4 consecutive float2 rows -> 2 x 16B aligned vector loads (broadcast)
        const ull* xr = xbase + (size_t)k2 * XT_STR;
        ulonglong2 xv01 = *(const ulonglong2*)(xr);
        ulonglong2 xv23 = *(const ulonglong2*)(xr + 2);
        ull xv[4] = { xv01.x, xv01.y, xv23.x, xv23.y };
        // 5 scalar 8B loads, conflict-free across tx
        const ull* wr = wbase + (size_t)k2 * HIDP;
        ull wv[5] = { wr[0], wr[1], wr[2], wr[3], wr[4] };
#pragma unroll
        for (int i = 0; i < 4; ++i)
#pragma unroll
            for (int c = 0; c < 5; ++c)
                ffma2(acc[i][c], xv[i], wv[c]);
    }

    // --- epilogue: tanh + dot(W1) + 16-lane reduce + mask + exp ---
    float w1c[5], spc[5];
#pragma unroll
    for (int c = 0; c < 5; ++c) {
        int j = tx * 5 + c;
        w1c[c] = w1s[j];
        spc[c] = spb_s[j];
    }
    const float b1v = b1[0];

#pragma unroll
    for (int i = 0; i < 4; ++i) {
        float s = 0.0f;
#pragma unroll
        for (int c = 0; c < 5; ++c) {
            ull a = acc[i][c];
            float lo = __uint_as_float((unsigned)(a & 0xffffffffu));
            float hi = __uint_as_float((unsigned)(a >> 32));
            float h  = lo + hi + spc[c];
            s = fmaf(tanhf(h), w1c[c], s);
        }
        s += __shfl_xor_sync(0xffffffffu, s, 1);
        s += __shfl_xor_sync(0xffffffffu, s, 2);
        s += __shfl_xor_sync(0xffffffffu, s, 4);
        s += __shfl_xor_sync(0xffffffffu, s, 8);
        if (tx == 0) {
            int r = r0 + i;
            size_t idx = (size_t)b * LL + l0 + r;
            float sv = s + b1v;
            if (cmask[idx] == 0) sv -= 1e30f;
            s1_out[idx] = sv;
            es[r] = expf(sv);          // masked -> exp(-1e30) = 0
        }
    }
    __syncthreads();

    // --- fused weighted partial sum from resident transposed tile ---
    if (tid < DIN) {
        const int f2   = tid >> 1;     // float2 index
        const int comp = tid & 1;
        const float* xcol = xs_t + (size_t)f2 * (XT_STR * 2) + comp;
        float p = 0.0f;
#pragma unroll 8
        for (int r = 0; r < TILE_L; ++r)
            p = fmaf(es[r], xcol[2 * r], p);
        g_part[b][chunk][tid] = p;
    } else if (tid < 160) {
        g_part[b][chunk][tid] = 0.0f;
    }
    // exp-sum: 4 warps cover the 128 rows
    if (tid < TILE_L) {
        float v = es[tid];
        v += __shfl_xor_sync(0xffffffffu, v, 16);
        v += __shfl_xor_sync(0xffffffffu, v, 8);
        v += __shfl_xor_sync(0xffffffffu, v, 4);
        v += __shfl_xor_sync(0xffffffffu, v, 2);
        v += __shfl_xor_sync(0xffffffffu, v, 1);
        if ((tid & 31) == 0) psred[tid >> 5] = v;
    }
    __syncthreads();
    if (tid == 0)
        g_psum[b][chunk] = (psred[0] + psred[1]) + (psred[2] + psred[3]);
}

// ---------------------------------------------------------------------------
// Kernel 3: finish — res[b][f] = sum_c part[b][c][f] / sum_c psum[b][c]
// ---------------------------------------------------------------------------
__global__ void k_finish(float* __restrict__ res) {
    const int b = blockIdx.x;
    const int f = threadIdx.x;         // 0..149
    float tot = 0.0f;
#pragma unroll
    for (int c = 0; c < NCHUNK; ++c) tot += g_psum[b][c];
    float p = 0.0f;
#pragma unroll
    for (int c = 0; c < NCHUNK; ++c) p += g_part[b][c][f];
    res[b * DIN + f] = p / tot;
}

// ---------------------------------------------------------------------------
extern "C" void kernel_launch(void* const* d_in, const int* in_sizes, int n_in,
                              void* d_out, int out_size) {
    const float* inputs = (const float*)d_in[0];
    const float* state  = (const float*)d_in[1];
    const int*   cmask  = (const int*)d_in[2];   // bool transported as int32 (verified R2)
    const float* W0     = (const float*)d_in[3];
    const float* b0     = (const float*)d_in[4];
    const float* W1     = (const float*)d_in[5];
    const float* b1     = (const float*)d_in[6];

    float* out = (float*)d_out;
    float* res = out;                 // [B][1][DIN] = 4800 floats
    float* s1  = out + BB * DIN;      // [B][L]      = 131072 floats

    const int smem2 = (K2N * XT_STR * 2 + K2N * HIDP * 2 + 2 * HIDP + TILE_L + 8)
                      * (int)sizeof(float);
    cudaFuncSetAttribute(k_scores, cudaFuncAttributeMaxDynamicSharedMemorySize, smem2);

    k_stateproj<<<BB, 320>>>(state, W0, b0);

    dim3 g2(NCHUNK, BB);
    k_scores<<<g2, NTH, smem2>>>(inputs, W0, W1, b1, cmask, s1);

    k_finish<<<BB, DIN>>>(res);
}

// round 8
// speedup vs baseline: 1.3114x; 1.3114x over previous
#include <cuda_runtime.h>
#include <math.h>
#include <stdint.h>

// Problem constants
#define BB     32
#define LL     4096
#define DIN    150
#define DST    75
#define HID    75
#define HIDP   80
#define K2N    75          // DIN/2 k-pairs
#define TILE_L 128
#define NCHUNK (LL / TILE_L)     // 32
#define WORKS  (BB * NCHUNK)     // 1024
#define GRIDC  148
#define NTH    256
#define TFLOATS (TILE_L * DIN)   // 19200 floats per x tile (flat row-major)
#define CHUNK16 (TFLOATS * 4 / 16)  // 4800 16B chunks per tile

typedef unsigned long long ull;

// cross-CTA reduction scratch
__device__ float g_part[BB][NCHUNK][160];
__device__ float g_psum[BB][NCHUNK];
__device__ int   g_done_b[BB];      // zero-init; reset by finisher each launch

__device__ __forceinline__ void ffma2(ull& d, ull a, ull b) {
    asm("fma.rn.f32x2 %0, %1, %2, %0;" : "+l"(d) : "l"(a), "l"(b));
}
__device__ __forceinline__ float tanh_approx(float x) {
    float t;
    asm("tanh.approx.f32 %0, %1;" : "=f"(t) : "f"(x));
    return t;
}
__device__ __forceinline__ void cp16(uint32_t saddr, const void* gptr) {
    asm volatile("cp.async.cg.shared.global [%0], [%1], 16;"
                 :: "r"(saddr), "l"(gptr));
}
__device__ __forceinline__ void cp_commit() {
    asm volatile("cp.async.commit_group;");
}
__device__ __forceinline__ void cp_wait1() {
    asm volatile("cp.async.wait_group 1;");
}
__device__ __forceinline__ void cp_wait0() {
    asm volatile("cp.async.wait_group 0;");
}

// ---------------------------------------------------------------------------
// Persistent fused kernel: scores GEMM + tanh/dot + mask + exp + weighted
// partial sums + per-batch finish. One CTA per SM; x tiles double-buffered
// via cp.async; W0 repack + state projections staged once per CTA.
// ---------------------------------------------------------------------------
__global__ __launch_bounds__(NTH, 1)
void k_fused(const float* __restrict__ inputs,
             const float* __restrict__ state,
             const int*   __restrict__ cmask,
             const float* __restrict__ W0,
             const float* __restrict__ b0,
             const float* __restrict__ W1,
             const float* __restrict__ b1,
             float* __restrict__ res,
             float* __restrict__ s1_out) {
    extern __shared__ float sm[];
    float* xs0     = sm;                       // [19200] tile buf 0 (flat)
    float* xs1     = sm + TFLOATS;             // [19200] tile buf 1
    float2* ws2    = (float2*)(sm + 2 * TFLOATS);   // [K2N][HIDP] k-pairs
    float* spb_all = sm + 2 * TFLOATS + K2N * HIDP * 2;  // [BB][HIDP]
    float* w1s     = spb_all + BB * HIDP;      // [HIDP]
    float* es      = w1s + HIDP;               // [TILE_L]
    float* psred   = es + TILE_L;              // [4]
    __shared__ int s_flag;

    const int tid = threadIdx.x;
    const int cta = blockIdx.x;
    const int nw  = (WORKS - cta + GRIDC - 1) / GRIDC;   // my work count

    // --- prefetch first tile into buf0 ---
    {
        int w0i = cta;
        int b = w0i >> 5, chunk = w0i & 31;
        const char* gbase = (const char*)(inputs + ((size_t)b * LL + chunk * TILE_L) * DIN);
        uint32_t sbase = (uint32_t)__cvta_generic_to_shared(xs0);
        for (int c = tid; c < CHUNK16; c += NTH)
            cp16(sbase + c * 16, gbase + (size_t)c * 16);
        cp_commit();
    }

    // --- stage W0 input-part repacked as k-pairs (once) ---
    for (int idx = tid; idx < K2N * HIDP; idx += NTH) {
        int k2 = idx / HIDP;
        int j  = idx - k2 * HIDP;
        float2 w;
        if (j < HID) {
            w.x = W0[(DST + 2 * k2)     * HID + j];
            w.y = W0[(DST + 2 * k2 + 1) * HID + j];
        } else { w.x = 0.0f; w.y = 0.0f; }
        ws2[idx] = w;
    }
    // --- state projections for all batches (once) ---
    for (int idx = tid; idx < BB * HIDP; idx += NTH) {
        int b = idx / HIDP;
        int j = idx - b * HIDP;
        float acc = 0.0f;
        if (j < HID) {
            acc = b0[j];
            const float* st = state + b * DST;
#pragma unroll 15
            for (int k = 0; k < DST; ++k)
                acc = fmaf(st[k], W0[k * HID + j], acc);
        }
        spb_all[idx] = acc;
    }
    if (tid < HIDP)
        w1s[tid] = (tid < HID) ? W1[tid] : 0.0f;

    const int tx = tid & 15;          // col group: cols tx*5 .. tx*5+4
    const int ty = tid >> 4;          // row group: rows ty*8 .. ty*8+7
    const int r0 = ty * 8;
    const float b1v = b1[0];

    float w1c[5];
#pragma unroll
    for (int c = 0; c < 5; ++c) w1c[c] = 0.0f;   // loaded after sync below

    // ---------------- persistent work loop ----------------
    for (int wi = 0; wi < nw; ++wi) {
        const int w     = cta + wi * GRIDC;
        const int b     = w >> 5;
        const int chunk = w & 31;
        const int l0    = chunk * TILE_L;
        float* xsb = (wi & 1) ? xs1 : xs0;

        // prefetch next tile into the other buffer
        if (wi + 1 < nw) {
            int w2 = cta + (wi + 1) * GRIDC;
            int b2 = w2 >> 5, ch2 = w2 & 31;
            const char* gbase = (const char*)(inputs + ((size_t)b2 * LL + ch2 * TILE_L) * DIN);
            float* dst = ((wi + 1) & 1) ? xs1 : xs0;
            uint32_t sbase = (uint32_t)__cvta_generic_to_shared(dst);
            for (int c = tid; c < CHUNK16; c += NTH)
                cp16(sbase + c * 16, gbase + (size_t)c * 16);
            cp_commit();
            cp_wait1();              // current buffer's group complete
        } else {
            cp_wait0();
        }
        __syncthreads();             // staging (wi==0: also ws2/spb) visible

        if (wi == 0) {
#pragma unroll
            for (int c = 0; c < 5; ++c) w1c[c] = w1s[tx * 5 + c];
        }

        // ---- GEMM: 8 rows x 5 col-pairs per thread, FFMA2 over 75 k-pairs
        ull acc[8][5];
#pragma unroll
        for (int i = 0; i < 8; ++i)
#pragma unroll
            for (int c = 0; c < 5; ++c) acc[i][c] = 0ULL;

        const ull* xb = (const ull*)xsb + (size_t)r0 * K2N;   // row-major, 75 ull/row
        const ull* wbase = (const ull*)ws2 + tx * 5;

#pragma unroll 5
        for (int k2 = 0; k2 < K2N; ++k2) {
            ull xv[8];
#pragma unroll
            for (int i = 0; i < 8; ++i)
                xv[i] = xb[(size_t)i * K2N + k2];
            const ull* wr = wbase + (size_t)k2 * HIDP;
            ull wv[5] = { wr[0], wr[1], wr[2], wr[3], wr[4] };
#pragma unroll
            for (int i = 0; i < 8; ++i)
#pragma unroll
                for (int c = 0; c < 5; ++c)
                    ffma2(acc[i][c], xv[i], wv[c]);
        }

        // ---- epilogue: tanh + dot(W1) + 16-lane reduce + mask + exp
        float spc[5];
#pragma unroll
        for (int c = 0; c < 5; ++c) spc[c] = spb_all[b * HIDP + tx * 5 + c];

#pragma unroll
        for (int i = 0; i < 8; ++i) {
            float s = 0.0f;
#pragma unroll
            for (int c = 0; c < 5; ++c) {
                ull a = acc[i][c];
                float lo = __uint_as_float((unsigned)(a & 0xffffffffu));
                float hi = __uint_as_float((unsigned)(a >> 32));
                float h  = lo + hi + spc[c];
                s = fmaf(tanh_approx(h), w1c[c], s);
            }
            s += __shfl_xor_sync(0xffffffffu, s, 1);
            s += __shfl_xor_sync(0xffffffffu, s, 2);
            s += __shfl_xor_sync(0xffffffffu, s, 4);
            s += __shfl_xor_sync(0xffffffffu, s, 8);
            if (tx == 0) {
                int r = r0 + i;
                size_t idx = (size_t)b * LL + l0 + r;
                float sv = s + b1v;
                if (cmask[idx] == 0) sv -= 1e30f;
                s1_out[idx] = sv;
                es[r] = __expf(sv);    // masked -> 0
            }
        }
        __syncthreads();

        // ---- fused weighted partial sums from resident tile
        if (tid < DIN) {
            const float* xcol = xsb + tid;
            float p = 0.0f;
#pragma unroll 8
            for (int r = 0; r < TILE_L; ++r)
                p = fmaf(es[r], xcol[(size_t)r * DIN], p);
            g_part[b][chunk][tid] = p;
        }
        if (tid < TILE_L) {
            float v = es[tid];
            v += __shfl_xor_sync(0xffffffffu, v, 16);
            v += __shfl_xor_sync(0xffffffffu, v, 8);
            v += __shfl_xor_sync(0xffffffffu, v, 4);
            v += __shfl_xor_sync(0xffffffffu, v, 2);
            v += __shfl_xor_sync(0xffffffffu, v, 1);
            if ((tid & 31) == 0) psred[tid >> 5] = v;
        }
        __syncthreads();
        if (tid == 0) {
            g_psum[b][chunk] = (psred[0] + psred[1]) + (psred[2] + psred[3]);
            __threadfence();
            int old = atomicAdd(&g_done_b[b], 1);
            s_flag = (old == NCHUNK - 1);
        }
        __syncthreads();

        // ---- last CTA to finish batch b computes res[b]
        if (s_flag) {
            __threadfence();
            if (tid < DIN) {
                float tot = 0.0f;
#pragma unroll
                for (int c = 0; c < NCHUNK; ++c) tot += g_psum[b][c];
                float p = 0.0f;
#pragma unroll
                for (int c = 0; c < NCHUNK; ++c) p += g_part[b][c][tid];
                res[b * DIN + tid] = p / tot;
            }
            if (tid == 0) g_done_b[b] = 0;   // reset for next launch/replay
        }
        __syncthreads();
    }
}

// ---------------------------------------------------------------------------
extern "C" void kernel_launch(void* const* d_in, const int* in_sizes, int n_in,
                              void* d_out, int out_size) {
    const float* inputs = (const float*)d_in[0];
    const float* state  = (const float*)d_in[1];
    const int*   cmask  = (const int*)d_in[2];   // bool transported as int32
    const float* W0     = (const float*)d_in[3];
    const float* b0     = (const float*)d_in[4];
    const float* W1     = (const float*)d_in[5];
    const float* b1     = (const float*)d_in[6];

    float* out = (float*)d_out;
    float* res = out;                 // [B][1][DIN] = 4800 floats
    float* s1  = out + BB * DIN;      // [B][L]      = 131072 floats

    const int smem = (2 * TFLOATS + K2N * HIDP * 2 + BB * HIDP + HIDP
                      + TILE_L + 4) * (int)sizeof(float);
    cudaFuncSetAttribute(k_fused, cudaFuncAttributeMaxDynamicSharedMemorySize, smem);

    k_fused<<<GRIDC, NTH, smem>>>(inputs, state, cmask, W0, b0, W1, b1, res, s1);
}